// round 4
// baseline (speedup 1.0000x reference)
#include <cuda_runtime.h>
#include <cuda_bf16.h>

#define BB   8
#define TLEN 32000
#define RES  64
#define GATE 128
#define SKC  64
#define CINC 80
#define NL   30
#define OUTC 256
#define TILE 128
#define NTH  256

#define SMEM_LAYER ((RES*TILE*2 + CINC*TILE) * 4)   /* 106496 bytes */
#define SMEM_FINAL (RES*TILE*2 * 4)                 /* 65536 bytes  */

typedef unsigned long long u64;

// ---------------- device scratch (no allocations allowed) ----------------
__device__ float g_hA[BB*RES*TLEN];
__device__ float g_hB[BB*RES*TLEN];
__device__ float g_skip[BB*SKC*TLEN];
__device__ float g_c[BB*CINC*TLEN];
__device__ float g_cA[BB*CINC*400];
__device__ float g_cB[BB*CINC*4000];
__device__ float g_Wg[NL*208*GATE];
__device__ float g_Wz[NL*64*GATE];
__device__ int   g_xflag;   // 1 => x stored as int32, 0 => int64

// ---------------- packed f32x2 helpers ----------------
__device__ __forceinline__ void ffma2(u64& acc, u64 ab, u64 h2) {
    asm("fma.rn.f32x2 %0, %1, %2, %0;" : "+l"(acc) : "l"(ab), "l"(h2));
}
__device__ __forceinline__ u64 pack2(float x) {
    u64 r;
    asm("mov.b64 %0, {%1, %1};" : "=l"(r) : "f"(x));
    return r;
}
__device__ __forceinline__ float2 unpack2(u64 v) {
    float2 r;
    asm("mov.b64 {%0, %1}, %2;" : "=f"(r.x), "=f"(r.y) : "l"(v));
    return r;
}

// ---------------- helpers ----------------
__device__ __forceinline__ float sigf(float x) {
    return __fdividef(1.f, 1.f + __expf(-x));
}
__device__ __forceinline__ float tanhfast(float x) {
    return 2.f * sigf(2.f * x) - 1.f;
}

// ---------------- dtype detection for x ----------------
__global__ void k_detect(const unsigned* __restrict__ xu) {
    __shared__ int s_any;
    if (threadIdx.x == 0) s_any = 0;
    __syncthreads();
    int any = 0;
    for (int i = 1 + 2*threadIdx.x; i < BB*TLEN; i += 2*blockDim.x)
        any |= (xu[i] != 0u);
    if (any) atomicOr(&s_any, 1);
    __syncthreads();
    if (threadIdx.x == 0) g_xflag = s_any;
}

// ---------------- first 1x1 conv (one-hot gather) + skip reset ----------------
__global__ void k_first(const void* __restrict__ xraw,
                        const float* __restrict__ fw,
                        const float* __restrict__ fb) {
    int g = blockIdx.x * blockDim.x + threadIdx.x;
    if (g >= BB*TLEN) return;
    int t = g % TLEN, b = g / TLEN;
    int xi = g_xflag ? ((const int*)xraw)[g]
                     : (int)(((const long long*)xraw)[g]);
    #pragma unroll 4
    for (int o = 0; o < RES; ++o) {
        g_hA[(b*RES + o)*TLEN + t]  = fw[o*OUTC + xi] + fb[o];
        g_skip[(b*SKC + o)*TLEN + t] = 0.f;
    }
}

// ---------------- weight packing (k-major) ----------------
__global__ void k_prep(const float* __restrict__ conv_w,
                       const float* __restrict__ cond_w,
                       const float* __restrict__ skip_w,
                       const float* __restrict__ out_w) {
    int i = blockIdx.x * blockDim.x + threadIdx.x;
    const int NG = NL*208*GATE;
    if (i < NG) {
        int l = i / (208*GATE);
        int rem = i % (208*GATE);
        int r = rem / GATE, o = rem % GATE;
        float v;
        if (r < 64)        v = conv_w[((l*GATE + o)*RES + r)*2 + 0];
        else if (r < 128)  v = conv_w[((l*GATE + o)*RES + (r-64))*2 + 1];
        else               v = cond_w[(l*GATE + o)*CINC + (r-128)];
        g_Wg[i] = v;
    } else {
        int j = i - NG;
        if (j < NL*64*GATE) {
            int l = j / (64*GATE);
            int rem = j % (64*GATE);
            int k = rem / GATE, o = rem % GATE;
            g_Wz[j] = (o < 64) ? skip_w[(l*SKC + o)*64 + k]
                               : out_w[(l*RES + (o-64))*64 + k];
        }
    }
}

// ---------------- conditioning upsample ----------------
__global__ void k_upA(const float* __restrict__ cond,
                      const float* __restrict__ cin_w) {
    int i = blockIdx.x * blockDim.x + threadIdx.x;
    if (i >= BB*CINC*400) return;
    int f = i % 400, o = (i/400) % CINC, b = i / (CINC*400);
    const float* cp = cond + b*CINC*400 + f;
    const float* wp = cin_w + o*CINC;
    float s = 0.f;
    #pragma unroll 8
    for (int k = 0; k < CINC; ++k) s += wp[k] * cp[k*400];
    g_cA[i] = s;
}

__global__ void k_upB() {
    int i = blockIdx.x * blockDim.x + threadIdx.x;
    if (i >= BB*CINC*4000) return;
    int t = i % 4000, bc = i / 4000;
    int lo = (t-10 < 0) ? 0 : t-10;
    int hi = (t+10 > 3999) ? 3999 : t+10;
    const float* src = g_cA + bc*400;
    float s = 0.f;
    for (int j = lo; j <= hi; ++j) s += src[j/10];
    g_cB[i] = s * (1.f/21.f);
}

__global__ void k_upC() {
    int i = blockIdx.x * blockDim.x + threadIdx.x;
    if (i >= BB*CINC*TLEN) return;
    int t = i % TLEN, bc = i / TLEN;
    int lo = (t-8 < 0) ? 0 : t-8;
    int hi = (t+8 > TLEN-1) ? TLEN-1 : t+8;
    const float* src = g_cB + bc*4000;
    float s = 0.f;
    for (int j = lo; j <= hi; ++j) s += src[j >> 3];
    g_c[i] = s * (1.f/17.f);
}

// ---------------- per-layer fused kernel (packed f32x2) ----------------
// Per thread: 4 output channels x 8 timestep-PAIRS.
// Pair p = tg + 8*j covers timesteps t = 2p, 2p+1  (p in 0..63).
__device__ __forceinline__ void gemm_acc2(const float* __restrict__ W,
                                          const float* __restrict__ S,
                                          int rows, int og, int tg,
                                          u64 acc[4][8]) {
    #pragma unroll 4
    for (int r = 0; r < rows; ++r) {
        float4 w = *(const float4*)(W + r*GATE + og*4);
        u64 w0 = pack2(w.x), w1 = pack2(w.y), w2 = pack2(w.z), w3 = pack2(w.w);
        const u64* sv = (const u64*)(S + r*TILE) + tg;
        #pragma unroll
        for (int j = 0; j < 8; ++j) {
            u64 h2 = sv[j*8];
            ffma2(acc[0][j], w0, h2);
            ffma2(acc[1][j], w1, h2);
            ffma2(acc[2][j], w2, h2);
            ffma2(acc[3][j], w3, h2);
        }
    }
}

__global__ void __launch_bounds__(NTH, 2) k_layer(int l, int d,
        const float* __restrict__ conv_b,
        const float* __restrict__ skip_b,
        const float* __restrict__ out_b) {
    extern __shared__ float sm[];
    float* sh_hc = sm;                   // [64][128]
    float* sh_hp = sm + RES*TILE;        // [64][128]
    float* sh_c  = sm + 2*RES*TILE;      // [80][128]
    float* sh_g  = sm + RES*TILE;        // [128][128], overlaps hp+c after sync

    const float* hin  = (l & 1) ? g_hB : g_hA;
    float*       hout = (l & 1) ? g_hA : g_hB;

    int b  = blockIdx.y;
    int t0 = blockIdx.x * TILE;
    int tid = threadIdx.x;
    const float* hb = hin + b*RES*TLEN;

    // load h(t) tile (vectorized)
    for (int i = tid; i < RES*(TILE/4); i += NTH) {
        int r = i >> 5, c4 = i & 31;
        ((float4*)sh_hc)[i] = *(const float4*)(hb + r*TLEN + t0 + c4*4);
    }
    // load h(t-d) tile with zero pad
    for (int i = tid; i < RES*TILE; i += NTH) {
        int r = i >> 7, c = i & (TILE-1);
        int t = t0 - d + c;
        sh_hp[i] = (t >= 0) ? hb[r*TLEN + t] : 0.f;
    }
    // load c tile
    const float* cb = g_c + b*CINC*TLEN;
    for (int i = tid; i < CINC*(TILE/4); i += NTH) {
        int r = i >> 5, c4 = i & 31;
        ((float4*)sh_c)[i] = *(const float4*)(cb + r*TLEN + t0 + c4*4);
    }
    __syncthreads();

    int og = tid >> 3;   // 0..31 -> output channels og*4..og*4+3
    int tg = tid & 7;    // pair phase

    // --- stage 1: g = W0 @ h(t-d) + W1 @ h(t) + Wc @ c + bias ---
    u64 acc[4][8];
    #pragma unroll
    for (int i = 0; i < 4; ++i) {
        u64 bi = pack2(conv_b[og*4 + i]);
        #pragma unroll
        for (int j = 0; j < 8; ++j) acc[i][j] = bi;
    }
    const float* Wl = g_Wg + (size_t)l*208*GATE;
    gemm_acc2(Wl,            sh_hp, 64, og, tg, acc);
    gemm_acc2(Wl + 64*GATE,  sh_hc, 64, og, tg, acc);
    gemm_acc2(Wl + 128*GATE, sh_c,  80, og, tg, acc);
    __syncthreads();   // done reading hp/c; reuse region for g

    #pragma unroll
    for (int i = 0; i < 4; ++i)
        #pragma unroll
        for (int j = 0; j < 8; ++j)
            *(u64*)(sh_g + (og*4 + i)*TILE + 2*(tg + 8*j)) = acc[i][j];
    __syncthreads();

    // --- gate: z = tanh(a) * sigmoid(b), in place over rows 0..63 ---
    for (int i = tid; i < 64*TILE; i += NTH) {
        float a  = sh_g[i];
        float bq = sh_g[i + 64*TILE];
        sh_g[i] = tanhfast(a) * sigf(bq);
    }
    __syncthreads();

    // --- stage 2: [skip_w; out_w] @ z ---
    u64 acc2[4][8];
    {
        const float* bias = (og < 16) ? (skip_b + og*4) : (out_b + (og-16)*4);
        #pragma unroll
        for (int i = 0; i < 4; ++i) {
            u64 bi = pack2(bias[i]);
            #pragma unroll
            for (int j = 0; j < 8; ++j) acc2[i][j] = bi;
        }
    }
    gemm_acc2(g_Wz + (size_t)l*64*GATE, sh_g, 64, og, tg, acc2);

    if (og < 16) {
        float2* sp = (float2*)(g_skip + (b*SKC + og*4)*TLEN + t0);
        #pragma unroll
        for (int i = 0; i < 4; ++i) {
            float2* row = sp + i*(TLEN/2);
            #pragma unroll
            for (int j = 0; j < 8; ++j) {
                float2 v = row[tg + 8*j];
                float2 a = unpack2(acc2[i][j]);
                v.x += a.x; v.y += a.y;
                row[tg + 8*j] = v;
            }
        }
    } else {
        int oo = (og - 16) * 4;
        #pragma unroll
        for (int i = 0; i < 4; ++i) {
            float2* row = (float2*)(hout + (b*RES + oo + i)*TLEN + t0);
            const float2* hcv = (const float2*)(sh_hc + (oo + i)*TILE);
            #pragma unroll
            for (int j = 0; j < 8; ++j) {
                float2 hc = hcv[tg + 8*j];
                float2 a  = unpack2(acc2[i][j]);
                hc.x += a.x; hc.y += a.y;
                row[tg + 8*j] = hc;
            }
        }
    }
}

// ---------------- output head: relu -> 64x64 -> relu -> 256x64 ----------------
__global__ void __launch_bounds__(NTH) k_final(const float* __restrict__ w1,
                                               const float* __restrict__ b1,
                                               const float* __restrict__ w2,
                                               const float* __restrict__ b2,
                                               float* __restrict__ out) {
    extern __shared__ float sm[];
    float* sh_s = sm;              // relu(skips) [64][128]
    float* sh_y = sm + RES*TILE;   // relu(y1)    [64][128]
    int b = blockIdx.y, t0 = blockIdx.x * TILE, tid = threadIdx.x;

    for (int i = tid; i < RES*(TILE/4); i += NTH) {
        int r = i >> 5, c4 = i & 31;
        float4 v = *(const float4*)(g_skip + (b*SKC + r)*TLEN + t0 + c4*4);
        v.x = fmaxf(v.x, 0.f); v.y = fmaxf(v.y, 0.f);
        v.z = fmaxf(v.z, 0.f); v.w = fmaxf(v.w, 0.f);
        ((float4*)sh_s)[i] = v;
    }
    __syncthreads();

    int og = tid >> 3, tg = tid & 7;   // og 0..31

    // phase A: y1 = relu(w1 @ s + b1), 2 channels per thread
    {
        u64 a0[8], a1[8];
        u64 c0 = pack2(b1[og*2]), c1 = pack2(b1[og*2+1]);
        #pragma unroll
        for (int j = 0; j < 8; ++j) { a0[j] = c0; a1[j] = c1; }
        #pragma unroll 4
        for (int r = 0; r < 64; ++r) {
            u64 w0 = pack2(w1[(og*2+0)*64 + r]);
            u64 w1v = pack2(w1[(og*2+1)*64 + r]);
            const u64* sv = (const u64*)(sh_s + r*TILE) + tg;
            #pragma unroll
            for (int j = 0; j < 8; ++j) {
                u64 s = sv[j*8];
                ffma2(a0[j], w0, s);
                ffma2(a1[j], w1v, s);
            }
        }
        #pragma unroll
        for (int j = 0; j < 8; ++j) {
            float2 v0 = unpack2(a0[j]), v1 = unpack2(a1[j]);
            v0.x = fmaxf(v0.x, 0.f); v0.y = fmaxf(v0.y, 0.f);
            v1.x = fmaxf(v1.x, 0.f); v1.y = fmaxf(v1.y, 0.f);
            *(float2*)(sh_y + (og*2+0)*TILE + 2*(tg + 8*j)) = v0;
            *(float2*)(sh_y + (og*2+1)*TILE + 2*(tg + 8*j)) = v1;
        }
    }
    __syncthreads();

    // phase B: y = w2 @ y1 + b2, 256 channels in two passes of 4/thread
    #pragma unroll 1
    for (int p = 0; p < 2; ++p) {
        int ob = p*128 + og*4;
        u64 acc[4][8];
        #pragma unroll
        for (int i = 0; i < 4; ++i) {
            u64 bi = pack2(b2[ob + i]);
            #pragma unroll
            for (int j = 0; j < 8; ++j) acc[i][j] = bi;
        }
        #pragma unroll 4
        for (int r = 0; r < 64; ++r) {
            u64 w0 = pack2(w2[(ob+0)*64 + r]);
            u64 w1v = pack2(w2[(ob+1)*64 + r]);
            u64 w2v = pack2(w2[(ob+2)*64 + r]);
            u64 w3v = pack2(w2[(ob+3)*64 + r]);
            const u64* yv = (const u64*)(sh_y + r*TILE) + tg;
            #pragma unroll
            for (int j = 0; j < 8; ++j) {
                u64 y = yv[j*8];
                ffma2(acc[0][j], w0, y);
                ffma2(acc[1][j], w1v, y);
                ffma2(acc[2][j], w2v, y);
                ffma2(acc[3][j], w3v, y);
            }
        }
        #pragma unroll
        for (int i = 0; i < 4; ++i) {
            float2* row = (float2*)(out + ((size_t)b*OUTC + ob + i)*TLEN + t0);
            #pragma unroll
            for (int j = 0; j < 8; ++j)
                row[tg + 8*j] = unpack2(acc[i][j]);
        }
    }
}

// ---------------- launch ----------------
extern "C" void kernel_launch(void* const* d_in, const int* in_sizes, int n_in,
                              void* d_out, int out_size) {
    (void)in_sizes; (void)n_in; (void)out_size;
    const void*  x       = d_in[0];
    const float* cond    = (const float*)d_in[1];
    const float* first_w = (const float*)d_in[2];
    const float* first_b = (const float*)d_in[3];
    const float* cin_w   = (const float*)d_in[4];
    const float* conv_w  = (const float*)d_in[5];
    const float* conv_b  = (const float*)d_in[6];
    const float* cond_w  = (const float*)d_in[7];
    const float* skip_w  = (const float*)d_in[8];
    const float* skip_b  = (const float*)d_in[9];
    const float* out_w   = (const float*)d_in[10];
    const float* out_b   = (const float*)d_in[11];
    const float* l1w     = (const float*)d_in[12];
    const float* l1b     = (const float*)d_in[13];
    const float* l2w     = (const float*)d_in[14];
    const float* l2b     = (const float*)d_in[15];
    float* out = (float*)d_out;

    cudaFuncSetAttribute(k_layer, cudaFuncAttributeMaxDynamicSharedMemorySize, SMEM_LAYER);
    cudaFuncSetAttribute(k_final, cudaFuncAttributeMaxDynamicSharedMemorySize, SMEM_FINAL);

    k_detect<<<1, 256>>>((const unsigned*)x);
    k_first<<<(BB*TLEN + 255)/256, 256>>>(x, first_w, first_b);

    int nprep = NL*208*GATE + NL*64*GATE;
    k_prep<<<(nprep + 255)/256, 256>>>(conv_w, cond_w, skip_w, out_w);

    k_upA<<<(BB*CINC*400  + 255)/256, 256>>>(cond, cin_w);
    k_upB<<<(BB*CINC*4000 + 255)/256, 256>>>();
    k_upC<<<(BB*CINC*TLEN + 255)/256, 256>>>();

    dim3 grid(TLEN/TILE, BB);
    for (int l = 0; l < NL; ++l) {
        int d = 1 << (l % 10);
        k_layer<<<grid, NTH, SMEM_LAYER>>>(l, d,
            conv_b + l*GATE, skip_b + l*SKC, out_b + l*RES);
    }
    k_final<<<grid, NTH, SMEM_FINAL>>>(l1w, l1b, l2w, l2b, out);
}

// round 9
// speedup vs baseline: 1.3189x; 1.3189x over previous
#include <cuda_runtime.h>
#include <cuda_bf16.h>
#include <cstdint>

#define BB   8
#define TLEN 32000
#define RES  64
#define GATE 128
#define SKC  64
#define CINC 80
#define NL   30
#define OUTC 256
#define TILE 128      /* head kernel time tile */
#define NTH  256      /* head kernel threads */
#define TT   128      /* layer time tile */
#define NTL  512      /* layer kernel threads (16 warps) */

#define AST 212       /* ACT smem stride (floats) */
#define GST 132       /* gate staging stride */
#define ZST 68        /* Z stride */
#define SM_Z (TT*AST*4)              /* 108544 */
#define SMEM_LAYER (SM_Z + TT*ZST*4) /* 143360 */
#define SMEM_FINAL (RES*TILE*2*4)    /* 65536  */

typedef unsigned int u32;
typedef unsigned long long ull;

/* ---------------- device scratch ---------------- */
__device__ __align__(256) float g_hA[BB*(size_t)TLEN*RES];    // [b][t][64]
__device__ __align__(256) float g_hB[BB*(size_t)TLEN*RES];
__device__ __align__(256) float g_skip[BB*(size_t)TLEN*SKC];  // [b][t][64]
__device__ __align__(256) float g_c[BB*(size_t)TLEN*CINC];    // [b][t][80]
__device__ __align__(256) float g_cA[BB*CINC*400];
__device__ __align__(256) float g_cB[BB*CINC*4000];
__device__ __align__(256) u32   g_W1pk[NL*26624];  // frag-packed tf32: [l][ks26][nt16][lane32][2]
__device__ __align__(256) u32   g_W2pk[NL*8192];   // [l][ks8][nt16][lane32][2]
__device__ __align__(256) float g_fwT[OUTC*RES];   // first_w^T + bias
__device__ int g_xflag;

/* ---------------- helpers ---------------- */
__device__ __forceinline__ u32 tf32r(float x) {
    u32 u; asm("cvt.rna.tf32.f32 %0, %1;" : "=r"(u) : "f"(x)); return u;
}
__device__ __forceinline__ void mma_tf32(float c[4], const u32 a[4], const u32 b[2]) {
    asm volatile("mma.sync.aligned.m16n8k8.row.col.f32.tf32.tf32.f32 "
        "{%0,%1,%2,%3}, {%4,%5,%6,%7}, {%8,%9}, {%0,%1,%2,%3};"
        : "+f"(c[0]), "+f"(c[1]), "+f"(c[2]), "+f"(c[3])
        : "r"(a[0]), "r"(a[1]), "r"(a[2]), "r"(a[3]), "r"(b[0]), "r"(b[1]));
}
__device__ __forceinline__ float sigf(float x) {
    return __fdividef(1.f, 1.f + __expf(-x));
}
__device__ __forceinline__ float tanhfast(float x) {
    return 2.f * sigf(2.f * x) - 1.f;
}
__device__ __forceinline__ void ffma2(ull& acc, ull ab, ull h2) {
    asm("fma.rn.f32x2 %0, %1, %2, %0;" : "+l"(acc) : "l"(ab), "l"(h2));
}
__device__ __forceinline__ ull pack2(float x) {
    ull r; asm("mov.b64 %0, {%1, %1};" : "=l"(r) : "f"(x)); return r;
}
__device__ __forceinline__ float2 unpack2(ull v) {
    float2 r; asm("mov.b64 {%0, %1}, %2;" : "=f"(r.x), "=f"(r.y) : "l"(v)); return r;
}

/* ---------------- dtype detect ---------------- */
__global__ void k_detect(const unsigned* __restrict__ xu) {
    __shared__ int s_any;
    if (threadIdx.x == 0) s_any = 0;
    __syncthreads();
    int any = 0;
    for (int i = 1 + 2*threadIdx.x; i < BB*TLEN; i += 2*blockDim.x)
        any |= (xu[i] != 0u);
    if (any) atomicOr(&s_any, 1);
    __syncthreads();
    if (threadIdx.x == 0) g_xflag = s_any;
}

/* ---------------- weight prep ---------------- */
__global__ void k_prep_fwt(const float* __restrict__ fw, const float* __restrict__ fb) {
    int i = blockIdx.x*blockDim.x + threadIdx.x;
    if (i >= OUTC*RES) return;
    int xi = i >> 6, o = i & 63;
    g_fwT[i] = fw[o*OUTC + xi] + fb[o];
}

__global__ void k_prep_w1(const float* __restrict__ conv_w, const float* __restrict__ cond_w) {
    int i = blockIdx.x*blockDim.x + threadIdx.x;
    if (i >= NL*26624) return;
    int l = i / 26624, r = i % 26624;
    int ks = r >> 10, rem = r & 1023;
    int nt = rem >> 6, rem2 = rem & 63;
    int lane = rem2 >> 1, reg = rem2 & 1;
    int k = ks*8 + (lane & 3) + 4*reg;   // 0..207
    int n = nt*8 + (lane >> 2);          // 0..127
    float f;
    if (k < 64)        f = conv_w[((l*GATE + n)*RES + k)*2 + 0];
    else if (k < 128)  f = conv_w[((l*GATE + n)*RES + (k-64))*2 + 1];
    else               f = cond_w[(l*GATE + n)*CINC + (k-128)];
    g_W1pk[i] = tf32r(f);
}

__global__ void k_prep_w2(const float* __restrict__ skip_w, const float* __restrict__ out_w) {
    int i = blockIdx.x*blockDim.x + threadIdx.x;
    if (i >= NL*8192) return;
    int l = i / 8192, r = i % 8192;
    int ks = r >> 10, rem = r & 1023;
    int nt = rem >> 6, rem2 = rem & 63;
    int lane = rem2 >> 1, reg = rem2 & 1;
    int k = ks*8 + (lane & 3) + 4*reg;   // 0..63
    int n = nt*8 + (lane >> 2);          // 0..127
    float f = (n < 64) ? skip_w[(l*SKC + n)*64 + k]
                       : out_w[(l*RES + (n-64))*64 + k];
    g_W2pk[i] = tf32r(f);
}

/* ---------------- first conv + skip reset ([b][t][ch]) ---------------- */
__global__ void k_first(const void* __restrict__ xraw) {
    int idx = blockIdx.x*blockDim.x + threadIdx.x;
    if (idx >= BB*TLEN*16) return;
    int q = idx & 15;
    int g = idx >> 4;
    int t = g % TLEN, b = g / TLEN;
    int xi = g_xflag ? ((const int*)xraw)[g]
                     : (int)(((const long long*)xraw)[g]);
    float4 v = ((const float4*)(g_fwT + xi*64))[q];
    size_t off = ((size_t)b*TLEN + t)*64 + q*4;
    *(float4*)(g_hA + off) = v;
    *(float4*)(g_skip + off) = make_float4(0.f, 0.f, 0.f, 0.f);
}

/* ---------------- conditioning upsample ---------------- */
__global__ void k_upA(const float* __restrict__ cond, const float* __restrict__ cin_w) {
    int i = blockIdx.x*blockDim.x + threadIdx.x;
    if (i >= BB*CINC*400) return;
    int f = i % 400, o = (i/400) % CINC, b = i / (CINC*400);
    const float* cp = cond + b*CINC*400 + f;
    const float* wp = cin_w + o*CINC;
    float s = 0.f;
    #pragma unroll 8
    for (int k = 0; k < CINC; ++k) s += wp[k] * cp[k*400];
    g_cA[i] = s;
}
__global__ void k_upB() {
    int i = blockIdx.x*blockDim.x + threadIdx.x;
    if (i >= BB*CINC*4000) return;
    int t = i % 4000, bc = i / 4000;
    int lo = (t-10 < 0) ? 0 : t-10;
    int hi = (t+10 > 3999) ? 3999 : t+10;
    const float* src = g_cA + bc*400;
    float s = 0.f;
    for (int j = lo; j <= hi; ++j) s += src[j/10];
    g_cB[i] = s * (1.f/21.f);
}
__global__ void k_upC() {
    int i = blockIdx.x*blockDim.x + threadIdx.x;
    if (i >= BB*CINC*TLEN) return;
    int t = i % TLEN, bc = i / TLEN;
    int ch = bc % CINC, b = bc / CINC;
    int lo = (t-8 < 0) ? 0 : t-8;
    int hi = (t+8 > TLEN-1) ? TLEN-1 : t+8;
    const float* src = g_cB + bc*4000;
    float s = 0.f;
    for (int j = lo; j <= hi; ++j) s += src[j >> 3];
    g_c[((size_t)b*TLEN + t)*CINC + ch] = s * (1.f/17.f);
}

/* ---------------- mma.sync tf32 layer kernel ---------------- */
__global__ void __launch_bounds__(NTL, 1) k_layer(int l, int d,
        const float* __restrict__ conv_b,
        const float* __restrict__ skip_b,
        const float* __restrict__ out_b) {
    extern __shared__ __align__(16) char smx[];
    u32*   ACTu = (u32*)smx;               // [128][AST] tf32 bits; becomes G after stage1
    float* G    = (float*)smx;             // [128][GST]
    u32*   Z    = (u32*)(smx + SM_Z);      // [128][ZST] tf32 bits

    int tid = threadIdx.x, lane = tid & 31, wid = tid >> 5;
    int gid = lane >> 2, tig = lane & 3;
    int tg = wid & 3, cg = wid >> 2;       // 4 time-groups x 4 channel-groups
    int b = blockIdx.y, t0 = blockIdx.x * TT;

    const float* hin  = ((l & 1) ? g_hB : g_hA) + (size_t)b*TLEN*64;
    float*       hout = ((l & 1) ? g_hA : g_hB) + (size_t)b*TLEN*64;
    const float* cbp  = g_c + (size_t)b*TLEN*CINC;

    /* ---- assemble ACT [t][k<208] (tf32 bits), k = hd(64) | h(64) | c(80) ---- */
    for (int idx = tid; idx < TT*52; idx += NTL) {
        int t = idx / 52, q = idx % 52;
        int k0 = q * 4;
        float4 v = make_float4(0.f, 0.f, 0.f, 0.f);
        int tt = t0 + t;
        if (k0 < 64) {
            int ts = tt - d;
            if (ts >= 0) v = *(const float4*)(hin + (size_t)ts*64 + k0);
        } else if (k0 < 128) {
            v = *(const float4*)(hin + (size_t)tt*64 + (k0 - 64));
        } else {
            v = *(const float4*)(cbp + (size_t)tt*CINC + (k0 - 128));
        }
        *(uint4*)(ACTu + t*AST + k0) =
            make_uint4(tf32r(v.x), tf32r(v.y), tf32r(v.z), tf32r(v.w));
    }
    __syncthreads();

    /* ---- stage 1: D1[128 t][128 gate ch], K=208 (26 k-steps) ---- */
    float acc[2][4][4];
    #pragma unroll
    for (int i = 0; i < 2; ++i)
        #pragma unroll
        for (int j = 0; j < 4; ++j)
            #pragma unroll
            for (int r = 0; r < 4; ++r) acc[i][j][r] = 0.f;

    const u32* W1p = g_W1pk + (size_t)l*26624;
    #pragma unroll 2
    for (int ks = 0; ks < 26; ++ks) {
        u32 a[2][4];
        int kk = ks*8 + tig;
        #pragma unroll
        for (int i = 0; i < 2; ++i) {
            int m = (tg*2 + i)*16 + gid;
            a[i][0] = ACTu[m*AST + kk];
            a[i][1] = ACTu[(m+8)*AST + kk];
            a[i][2] = ACTu[m*AST + kk + 4];
            a[i][3] = ACTu[(m+8)*AST + kk + 4];
        }
        #pragma unroll
        for (int j = 0; j < 4; ++j) {
            int nt = cg*4 + j;
            uint2 bv = __ldg((const uint2*)(W1p + ((ks*16 + nt)*32 + lane)*2));
            u32 bb[2] = {bv.x, bv.y};
            mma_tf32(acc[0][j], a[0], bb);
            mma_tf32(acc[1][j], a[1], bb);
        }
    }
    __syncthreads();   /* all ACT reads complete before G overwrite */

    /* ---- epilogue 1: write gates to G ---- */
    #pragma unroll
    for (int i = 0; i < 2; ++i) {
        int m0 = (tg*2 + i)*16 + gid;
        #pragma unroll
        for (int j = 0; j < 4; ++j) {
            int n0 = cg*32 + j*8 + 2*tig;
            *(float2*)&G[m0*GST + n0]     = make_float2(acc[i][j][0], acc[i][j][1]);
            *(float2*)&G[(m0+8)*GST + n0] = make_float2(acc[i][j][2], acc[i][j][3]);
        }
    }
    __syncthreads();

    /* ---- gate: z = tanh(a)*sigmoid(b) -> Z (tf32 bits) ---- */
    for (int idx = tid; idx < TT*64; idx += NTL) {
        int t = idx >> 6, ch = idx & 63;
        float av = G[t*GST + ch]      + conv_b[ch];
        float bv = G[t*GST + 64 + ch] + conv_b[64 + ch];
        Z[t*ZST + ch] = tf32r(tanhfast(av) * sigf(bv));
    }
    __syncthreads();

    /* ---- stage 2: D2[128 t][skip64|out64], K=64 (8 k-steps) ---- */
    float acc2[2][4][4];
    #pragma unroll
    for (int i = 0; i < 2; ++i)
        #pragma unroll
        for (int j = 0; j < 4; ++j)
            #pragma unroll
            for (int r = 0; r < 4; ++r) acc2[i][j][r] = 0.f;

    const u32* W2p = g_W2pk + (size_t)l*8192;
    #pragma unroll
    for (int ks = 0; ks < 8; ++ks) {
        u32 a[2][4];
        int kk = ks*8 + tig;
        #pragma unroll
        for (int i = 0; i < 2; ++i) {
            int m = (tg*2 + i)*16 + gid;
            a[i][0] = Z[m*ZST + kk];
            a[i][1] = Z[(m+8)*ZST + kk];
            a[i][2] = Z[m*ZST + kk + 4];
            a[i][3] = Z[(m+8)*ZST + kk + 4];
        }
        #pragma unroll
        for (int j = 0; j < 4; ++j) {
            int nt = cg*4 + j;
            uint2 bv = __ldg((const uint2*)(W2p + ((ks*16 + nt)*32 + lane)*2));
            u32 bb[2] = {bv.x, bv.y};
            mma_tf32(acc2[0][j], a[0], bb);
            mma_tf32(acc2[1][j], a[1], bb);
        }
    }

    /* ---- epilogue 2: skip RMW + residual h ---- */
    #pragma unroll
    for (int i = 0; i < 2; ++i) {
        int m0 = (tg*2 + i)*16 + gid;
        #pragma unroll
        for (int j = 0; j < 4; ++j) {
            int n0 = cg*32 + j*8 + 2*tig;
            #pragma unroll
            for (int h2 = 0; h2 < 2; ++h2) {
                int t = t0 + m0 + 8*h2;
                float v0 = acc2[i][j][2*h2], v1 = acc2[i][j][2*h2 + 1];
                if (n0 < 64) {
                    float2* sp = (float2*)&g_skip[((size_t)b*TLEN + t)*64 + n0];
                    float2 cur = *sp;
                    cur.x += v0 + skip_b[n0];
                    cur.y += v1 + skip_b[n0 + 1];
                    *sp = cur;
                } else {
                    int o = n0 - 64;
                    float2 hv = *(const float2*)&hin[(size_t)t*64 + o];
                    float2 r = make_float2(hv.x + v0 + out_b[o],
                                           hv.y + v1 + out_b[o + 1]);
                    *(float2*)&hout[(size_t)t*64 + o] = r;
                }
            }
        }
    }
}

/* ---------------- output head (FFMA2, transpose-load skip) ---------------- */
__global__ void __launch_bounds__(NTH) k_final(const float* __restrict__ w1,
                                               const float* __restrict__ b1,
                                               const float* __restrict__ w2,
                                               const float* __restrict__ b2,
                                               float* __restrict__ out) {
    extern __shared__ float sm[];
    float* sh_s = sm;              // relu(skips) [64][128]
    float* sh_y = sm + RES*TILE;   // relu(y1)    [64][128]
    int b = blockIdx.y, t0 = blockIdx.x * TILE, tid = threadIdx.x;

    for (int idx = tid; idx < 16*TILE; idx += NTH) {
        int t = idx & (TILE-1), q = idx >> 7;
        float4 v = *(const float4*)(g_skip + ((size_t)b*TLEN + t0 + t)*64 + q*4);
        sh_s[(q*4+0)*TILE + t] = fmaxf(v.x, 0.f);
        sh_s[(q*4+1)*TILE + t] = fmaxf(v.y, 0.f);
        sh_s[(q*4+2)*TILE + t] = fmaxf(v.z, 0.f);
        sh_s[(q*4+3)*TILE + t] = fmaxf(v.w, 0.f);
    }
    __syncthreads();

    int og = tid >> 3, tg = tid & 7;

    {
        ull a0[8], a1[8];
        ull c0 = pack2(b1[og*2]), c1 = pack2(b1[og*2+1]);
        #pragma unroll
        for (int j = 0; j < 8; ++j) { a0[j] = c0; a1[j] = c1; }
        #pragma unroll 4
        for (int r = 0; r < 64; ++r) {
            ull w0 = pack2(w1[(og*2+0)*64 + r]);
            ull w1v = pack2(w1[(og*2+1)*64 + r]);
            const ull* sv = (const ull*)(sh_s + r*TILE) + tg;
            #pragma unroll
            for (int j = 0; j < 8; ++j) {
                ull s = sv[j*8];
                ffma2(a0[j], w0, s);
                ffma2(a1[j], w1v, s);
            }
        }
        #pragma unroll
        for (int j = 0; j < 8; ++j) {
            float2 v0 = unpack2(a0[j]), v1 = unpack2(a1[j]);
            v0.x = fmaxf(v0.x, 0.f); v0.y = fmaxf(v0.y, 0.f);
            v1.x = fmaxf(v1.x, 0.f); v1.y = fmaxf(v1.y, 0.f);
            *(float2*)(sh_y + (og*2+0)*TILE + 2*(tg + 8*j)) = v0;
            *(float2*)(sh_y + (og*2+1)*TILE + 2*(tg + 8*j)) = v1;
        }
    }
    __syncthreads();

    #pragma unroll 1
    for (int p = 0; p < 2; ++p) {
        int ob = p*128 + og*4;
        ull acc[4][8];
        #pragma unroll
        for (int i = 0; i < 4; ++i) {
            ull bi = pack2(b2[ob + i]);
            #pragma unroll
            for (int j = 0; j < 8; ++j) acc[i][j] = bi;
        }
        #pragma unroll 4
        for (int r = 0; r < 64; ++r) {
            ull w0 = pack2(w2[(ob+0)*64 + r]);
            ull w1v = pack2(w2[(ob+1)*64 + r]);
            ull w2v = pack2(w2[(ob+2)*64 + r]);
            ull w3v = pack2(w2[(ob+3)*64 + r]);
            const ull* yv = (const ull*)(sh_y + r*TILE) + tg;
            #pragma unroll
            for (int j = 0; j < 8; ++j) {
                ull y = yv[j*8];
                ffma2(acc[0][j], w0, y);
                ffma2(acc[1][j], w1v, y);
                ffma2(acc[2][j], w2v, y);
                ffma2(acc[3][j], w3v, y);
            }
        }
        #pragma unroll
        for (int i = 0; i < 4; ++i) {
            float2* row = (float2*)(out + ((size_t)b*OUTC + ob + i)*TLEN + t0);
            #pragma unroll
            for (int j = 0; j < 8; ++j)
                row[tg + 8*j] = unpack2(acc[i][j]);
        }
    }
}

/* ---------------- launch ---------------- */
extern "C" void kernel_launch(void* const* d_in, const int* in_sizes, int n_in,
                              void* d_out, int out_size) {
    (void)in_sizes; (void)n_in; (void)out_size;
    const void*  x       = d_in[0];
    const float* cond    = (const float*)d_in[1];
    const float* first_w = (const float*)d_in[2];
    const float* first_b = (const float*)d_in[3];
    const float* cin_w   = (const float*)d_in[4];
    const float* conv_w  = (const float*)d_in[5];
    const float* conv_b  = (const float*)d_in[6];
    const float* cond_w  = (const float*)d_in[7];
    const float* skip_w  = (const float*)d_in[8];
    const float* skip_b  = (const float*)d_in[9];
    const float* out_w   = (const float*)d_in[10];
    const float* out_b   = (const float*)d_in[11];
    const float* l1w     = (const float*)d_in[12];
    const float* l1b     = (const float*)d_in[13];
    const float* l2w     = (const float*)d_in[14];
    const float* l2b     = (const float*)d_in[15];
    float* out = (float*)d_out;

    cudaFuncSetAttribute(k_layer, cudaFuncAttributeMaxDynamicSharedMemorySize, SMEM_LAYER);
    cudaFuncSetAttribute(k_final, cudaFuncAttributeMaxDynamicSharedMemorySize, SMEM_FINAL);

    k_detect<<<1, 256>>>((const unsigned*)x);
    k_prep_fwt<<<(OUTC*RES + 255)/256, 256>>>(first_w, first_b);
    k_prep_w1<<<(NL*26624 + 255)/256, 256>>>(conv_w, cond_w);
    k_prep_w2<<<(NL*8192 + 255)/256, 256>>>(skip_w, out_w);

    k_upA<<<(BB*CINC*400  + 255)/256, 256>>>(cond, cin_w);
    k_upB<<<(BB*CINC*4000 + 255)/256, 256>>>();
    k_upC<<<(BB*CINC*TLEN + 255)/256, 256>>>();

    k_first<<<(BB*TLEN*16 + 255)/256, 256>>>(x);

    dim3 gridL(TLEN/TT, BB);
    for (int l = 0; l < NL; ++l) {
        int d = 1 << (l % 10);
        k_layer<<<gridL, NTL, SMEM_LAYER>>>(l, d,
            conv_b + l*GATE, skip_b + l*SKC, out_b + l*RES);
    }
    dim3 gridF(TLEN/TILE, BB);
    k_final<<<gridF, NTH, SMEM_FINAL>>>(l1w, l1b, l2w, l2b, out);
}

// round 10
// speedup vs baseline: 1.5519x; 1.1767x over previous
#include <cuda_runtime.h>
#include <cuda_fp16.h>
#include <cuda_bf16.h>
#include <cstdint>

#define BB   8
#define TLEN 32000
#define RES  64
#define GATE 128
#define SKC  64
#define CINC 80
#define NL   30
#define OUTC 256
#define TILE 128      /* head kernel time tile */
#define NTH  256      /* head kernel threads */
#define TT   128      /* layer time tile */
#define NTL  512      /* layer kernel threads (16 warps) */

#define AST2 108      /* ACT stride in half2 units (216 halves, conflict-free) */
#define GST  132      /* gate staging stride (floats) */
#define ZST2 36       /* Z stride in half2 units */
#define SM_Z 67584    /* max(ACT 55296, G 67584) */
#define SMEM_LAYER (SM_Z + TT*ZST2*4)  /* 86016 */
#define SMEM_FINAL (RES*TILE*2*4)      /* 65536 */

typedef unsigned int u32;
typedef unsigned long long ull;

/* ---------------- device scratch ---------------- */
__device__ __align__(256) float g_hA[BB*(size_t)TLEN*RES];    // [b][t][64]
__device__ __align__(256) float g_hB[BB*(size_t)TLEN*RES];
__device__ __align__(256) float g_skip[BB*(size_t)TLEN*SKC];  // [b][t][64]
__device__ __align__(256) float g_c[BB*(size_t)TLEN*CINC];    // [b][t][80]
__device__ __align__(256) float g_cA[BB*CINC*400];
__device__ __align__(256) float g_cB[BB*CINC*4000];
__device__ __align__(256) u32   g_W1pk[NL*13312];  // fp16 frag-packed: [l][ks13][nt16][lane32][2]
__device__ __align__(256) u32   g_W2pk[NL*4096];   // [l][ks4][nt16][lane32][2]
__device__ __align__(256) float g_fwT[OUTC*RES];   // first_w^T + bias
__device__ int g_xflag;

/* ---------------- helpers ---------------- */
__device__ __forceinline__ u32 h2bits(float a, float b) {
    __half2 h = __floats2half2_rn(a, b);
    return *(u32*)&h;
}
__device__ __forceinline__ void mma_f16(float c[4], const u32 a[4], const u32 b[2]) {
    asm volatile("mma.sync.aligned.m16n8k16.row.col.f32.f16.f16.f32 "
        "{%0,%1,%2,%3}, {%4,%5,%6,%7}, {%8,%9}, {%0,%1,%2,%3};"
        : "+f"(c[0]), "+f"(c[1]), "+f"(c[2]), "+f"(c[3])
        : "r"(a[0]), "r"(a[1]), "r"(a[2]), "r"(a[3]), "r"(b[0]), "r"(b[1]));
}
__device__ __forceinline__ float sigf(float x) {
    return __fdividef(1.f, 1.f + __expf(-x));
}
__device__ __forceinline__ float tanhfast(float x) {
    return 2.f * sigf(2.f * x) - 1.f;
}
__device__ __forceinline__ void ffma2(ull& acc, ull ab, ull h2) {
    asm("fma.rn.f32x2 %0, %1, %2, %0;" : "+l"(acc) : "l"(ab), "l"(h2));
}
__device__ __forceinline__ ull pack2(float x) {
    ull r; asm("mov.b64 %0, {%1, %1};" : "=l"(r) : "f"(x)); return r;
}
__device__ __forceinline__ float2 unpack2(ull v) {
    float2 r; asm("mov.b64 {%0, %1}, %2;" : "=f"(r.x), "=f"(r.y) : "l"(v)); return r;
}

/* ---------------- dtype detect ---------------- */
__global__ void k_detect(const unsigned* __restrict__ xu) {
    __shared__ int s_any;
    if (threadIdx.x == 0) s_any = 0;
    __syncthreads();
    int any = 0;
    for (int i = 1 + 2*threadIdx.x; i < BB*TLEN; i += 2*blockDim.x)
        any |= (xu[i] != 0u);
    if (any) atomicOr(&s_any, 1);
    __syncthreads();
    if (threadIdx.x == 0) g_xflag = s_any;
}

/* ---------------- weight prep ---------------- */
__global__ void k_prep_fwt(const float* __restrict__ fw, const float* __restrict__ fb) {
    int i = blockIdx.x*blockDim.x + threadIdx.x;
    if (i >= OUTC*RES) return;
    int xi = i >> 6, o = i & 63;
    g_fwT[i] = fw[o*OUTC + xi] + fb[o];
}

__device__ __forceinline__ float w1_elem(const float* conv_w, const float* cond_w,
                                         int l, int n, int k) {
    if (k < 64)        return conv_w[((l*GATE + n)*RES + k)*2 + 0];
    else if (k < 128)  return conv_w[((l*GATE + n)*RES + (k-64))*2 + 1];
    else               return cond_w[(l*GATE + n)*CINC + (k-128)];
}

__global__ void k_prep_w1(const float* __restrict__ conv_w, const float* __restrict__ cond_w) {
    int i = blockIdx.x*blockDim.x + threadIdx.x;
    if (i >= NL*13312) return;
    int l = i / 13312, r = i % 13312;
    int ks = r >> 10, rem = r & 1023;
    int nt = rem >> 6, rem2 = rem & 63;
    int lane = rem2 >> 1, reg = rem2 & 1;
    int k0 = ks*16 + 2*(lane & 3) + 8*reg;   // 0..207 (even)
    int n  = nt*8 + (lane >> 2);
    g_W1pk[i] = h2bits(w1_elem(conv_w, cond_w, l, n, k0),
                       w1_elem(conv_w, cond_w, l, n, k0 + 1));
}

__global__ void k_prep_w2(const float* __restrict__ skip_w, const float* __restrict__ out_w) {
    int i = blockIdx.x*blockDim.x + threadIdx.x;
    if (i >= NL*4096) return;
    int l = i / 4096, r = i % 4096;
    int ks = r >> 10, rem = r & 1023;
    int nt = rem >> 6, rem2 = rem & 63;
    int lane = rem2 >> 1, reg = rem2 & 1;
    int k0 = ks*16 + 2*(lane & 3) + 8*reg;   // 0..63 (even)
    int n  = nt*8 + (lane >> 2);
    float f0 = (n < 64) ? skip_w[(l*SKC + n)*64 + k0]
                        : out_w[(l*RES + (n-64))*64 + k0];
    float f1 = (n < 64) ? skip_w[(l*SKC + n)*64 + k0 + 1]
                        : out_w[(l*RES + (n-64))*64 + k0 + 1];
    g_W2pk[i] = h2bits(f0, f1);
}

/* ---------------- first conv + skip reset ([b][t][ch]) ---------------- */
__global__ void k_first(const void* __restrict__ xraw) {
    int idx = blockIdx.x*blockDim.x + threadIdx.x;
    if (idx >= BB*TLEN*16) return;
    int q = idx & 15;
    int g = idx >> 4;
    int t = g % TLEN, b = g / TLEN;
    int xi = g_xflag ? ((const int*)xraw)[g]
                     : (int)(((const long long*)xraw)[g]);
    float4 v = ((const float4*)(g_fwT + xi*64))[q];
    size_t off = ((size_t)b*TLEN + t)*64 + q*4;
    *(float4*)(g_hA + off) = v;
    *(float4*)(g_skip + off) = make_float4(0.f, 0.f, 0.f, 0.f);
}

/* ---------------- conditioning upsample ---------------- */
__global__ void k_upA(const float* __restrict__ cond, const float* __restrict__ cin_w) {
    int i = blockIdx.x*blockDim.x + threadIdx.x;
    if (i >= BB*CINC*400) return;
    int f = i % 400, o = (i/400) % CINC, b = i / (CINC*400);
    const float* cp = cond + b*CINC*400 + f;
    const float* wp = cin_w + o*CINC;
    float s = 0.f;
    #pragma unroll 8
    for (int k = 0; k < CINC; ++k) s += wp[k] * cp[k*400];
    g_cA[i] = s;
}
__global__ void k_upB() {
    int i = blockIdx.x*blockDim.x + threadIdx.x;
    if (i >= BB*CINC*4000) return;
    int t = i % 4000, bc = i / 4000;
    int lo = (t-10 < 0) ? 0 : t-10;
    int hi = (t+10 > 3999) ? 3999 : t+10;
    const float* src = g_cA + bc*400;
    float s = 0.f;
    for (int j = lo; j <= hi; ++j) s += src[j/10];
    g_cB[i] = s * (1.f/21.f);
}
__global__ void k_upC() {
    int i = blockIdx.x*blockDim.x + threadIdx.x;
    if (i >= BB*CINC*TLEN) return;
    int t = i % TLEN, bc = i / TLEN;
    int ch = bc % CINC, b = bc / CINC;
    int lo = (t-8 < 0) ? 0 : t-8;
    int hi = (t+8 > TLEN-1) ? TLEN-1 : t+8;
    const float* src = g_cB + bc*4000;
    float s = 0.f;
    for (int j = lo; j <= hi; ++j) s += src[j >> 3];
    g_c[((size_t)b*TLEN + t)*CINC + ch] = s * (1.f/17.f);
}

/* ---------------- fp16 mma.sync layer kernel ---------------- */
__global__ void __launch_bounds__(NTL, 1) k_layer(int l, int d,
        const float* __restrict__ conv_b,
        const float* __restrict__ skip_b,
        const float* __restrict__ out_b) {
    extern __shared__ __align__(16) char smx[];
    u32*   ACT2 = (u32*)smx;               // [128][AST2] half2; becomes G after stage1
    float* G    = (float*)smx;             // [128][GST]
    u32*   Z2   = (u32*)(smx + SM_Z);      // [128][ZST2] half2

    int tid = threadIdx.x, lane = tid & 31, wid = tid >> 5;
    int gid = lane >> 2, tig = lane & 3;
    int tg = wid & 3, cg = wid >> 2;       // 4 time-groups x 4 channel-groups
    int b = blockIdx.y, t0 = blockIdx.x * TT;

    const float* hin  = ((l & 1) ? g_hB : g_hA) + (size_t)b*TLEN*64;
    float*       hout = ((l & 1) ? g_hA : g_hB) + (size_t)b*TLEN*64;
    const float* cbp  = g_c + (size_t)b*TLEN*CINC;

    /* ---- assemble ACT [t][k<208 halves], k = hd(64) | h(64) | c(80) ---- */
    for (int idx = tid; idx < TT*52; idx += NTL) {
        int t = idx / 52, q = idx % 52;    // k0 = q*4 halves
        int k0 = q * 4;
        float4 v = make_float4(0.f, 0.f, 0.f, 0.f);
        int tt = t0 + t;
        if (k0 < 64) {
            int ts = tt - d;
            if (ts >= 0) v = *(const float4*)(hin + (size_t)ts*64 + k0);
        } else if (k0 < 128) {
            v = *(const float4*)(hin + (size_t)tt*64 + (k0 - 64));
        } else {
            v = *(const float4*)(cbp + (size_t)tt*CINC + (k0 - 128));
        }
        *(uint2*)(ACT2 + t*AST2 + q*2) =
            make_uint2(h2bits(v.x, v.y), h2bits(v.z, v.w));
    }
    __syncthreads();

    /* ---- stage 1: D1[128 t][128 gate ch], K=208 (13 k-steps) ---- */
    float acc[2][4][4];
    #pragma unroll
    for (int i = 0; i < 2; ++i)
        #pragma unroll
        for (int j = 0; j < 4; ++j)
            #pragma unroll
            for (int r = 0; r < 4; ++r) acc[i][j][r] = 0.f;

    const u32* W1p = g_W1pk + (size_t)l*13312;
    #pragma unroll 2
    for (int ks = 0; ks < 13; ++ks) {
        u32 a[2][4];
        int kk = ks*8 + tig;               // half2 index
        #pragma unroll
        for (int i = 0; i < 2; ++i) {
            int m = (tg*2 + i)*16 + gid;
            a[i][0] = ACT2[m*AST2 + kk];
            a[i][1] = ACT2[(m+8)*AST2 + kk];
            a[i][2] = ACT2[m*AST2 + kk + 4];
            a[i][3] = ACT2[(m+8)*AST2 + kk + 4];
        }
        #pragma unroll
        for (int j = 0; j < 4; ++j) {
            int nt = cg*4 + j;
            uint2 bv = __ldg((const uint2*)(W1p + ((ks*16 + nt)*32 + lane)*2));
            u32 bb[2] = {bv.x, bv.y};
            mma_f16(acc[0][j], a[0], bb);
            mma_f16(acc[1][j], a[1], bb);
        }
    }
    __syncthreads();   /* all ACT reads complete before G overwrite */

    /* ---- epilogue 1: write gates to G ---- */
    #pragma unroll
    for (int i = 0; i < 2; ++i) {
        int m0 = (tg*2 + i)*16 + gid;
        #pragma unroll
        for (int j = 0; j < 4; ++j) {
            int n0 = cg*32 + j*8 + 2*tig;
            *(float2*)&G[m0*GST + n0]     = make_float2(acc[i][j][0], acc[i][j][1]);
            *(float2*)&G[(m0+8)*GST + n0] = make_float2(acc[i][j][2], acc[i][j][3]);
        }
    }
    __syncthreads();

    /* ---- gate: z = tanh(a)*sigmoid(b) -> Z (half2) ---- */
    for (int idx = tid; idx < TT*32; idx += NTL) {
        int t = idx >> 5, c2 = idx & 31;
        int ch = c2*2;
        float a0 = G[t*GST + ch]     + conv_b[ch];
        float a1 = G[t*GST + ch + 1] + conv_b[ch + 1];
        float b0 = G[t*GST + 64 + ch]     + conv_b[64 + ch];
        float b1 = G[t*GST + 64 + ch + 1] + conv_b[64 + ch + 1];
        Z2[t*ZST2 + c2] = h2bits(tanhfast(a0) * sigf(b0),
                                 tanhfast(a1) * sigf(b1));
    }
    __syncthreads();

    /* ---- stage 2: D2[128 t][skip64|out64], K=64 (4 k-steps) ---- */
    float acc2[2][4][4];
    #pragma unroll
    for (int i = 0; i < 2; ++i)
        #pragma unroll
        for (int j = 0; j < 4; ++j)
            #pragma unroll
            for (int r = 0; r < 4; ++r) acc2[i][j][r] = 0.f;

    const u32* W2p = g_W2pk + (size_t)l*4096;
    #pragma unroll
    for (int ks = 0; ks < 4; ++ks) {
        u32 a[2][4];
        int kk = ks*8 + tig;
        #pragma unroll
        for (int i = 0; i < 2; ++i) {
            int m = (tg*2 + i)*16 + gid;
            a[i][0] = Z2[m*ZST2 + kk];
            a[i][1] = Z2[(m+8)*ZST2 + kk];
            a[i][2] = Z2[m*ZST2 + kk + 4];
            a[i][3] = Z2[(m+8)*ZST2 + kk + 4];
        }
        #pragma unroll
        for (int j = 0; j < 4; ++j) {
            int nt = cg*4 + j;
            uint2 bv = __ldg((const uint2*)(W2p + ((ks*16 + nt)*32 + lane)*2));
            u32 bb[2] = {bv.x, bv.y};
            mma_f16(acc2[0][j], a[0], bb);
            mma_f16(acc2[1][j], a[1], bb);
        }
    }

    /* ---- epilogue 2: skip RMW + residual h ---- */
    #pragma unroll
    for (int i = 0; i < 2; ++i) {
        int m0 = (tg*2 + i)*16 + gid;
        #pragma unroll
        for (int j = 0; j < 4; ++j) {
            int n0 = cg*32 + j*8 + 2*tig;
            #pragma unroll
            for (int h2 = 0; h2 < 2; ++h2) {
                int t = t0 + m0 + 8*h2;
                float v0 = acc2[i][j][2*h2], v1 = acc2[i][j][2*h2 + 1];
                if (n0 < 64) {
                    float2* sp = (float2*)&g_skip[((size_t)b*TLEN + t)*64 + n0];
                    float2 cur = *sp;
                    cur.x += v0 + skip_b[n0];
                    cur.y += v1 + skip_b[n0 + 1];
                    *sp = cur;
                } else {
                    int o = n0 - 64;
                    float2 hv = *(const float2*)&hin[(size_t)t*64 + o];
                    float2 r = make_float2(hv.x + v0 + out_b[o],
                                           hv.y + v1 + out_b[o + 1]);
                    *(float2*)&hout[(size_t)t*64 + o] = r;
                }
            }
        }
    }
}

/* ---------------- output head (FFMA2, transpose-load skip) ---------------- */
__global__ void __launch_bounds__(NTH) k_final(const float* __restrict__ w1,
                                               const float* __restrict__ b1,
                                               const float* __restrict__ w2,
                                               const float* __restrict__ b2,
                                               float* __restrict__ out) {
    extern __shared__ float sm[];
    float* sh_s = sm;              // relu(skips) [64][128]
    float* sh_y = sm + RES*TILE;   // relu(y1)    [64][128]
    int b = blockIdx.y, t0 = blockIdx.x * TILE, tid = threadIdx.x;

    for (int idx = tid; idx < 16*TILE; idx += NTH) {
        int t = idx & (TILE-1), q = idx >> 7;
        float4 v = *(const float4*)(g_skip + ((size_t)b*TLEN + t0 + t)*64 + q*4);
        sh_s[(q*4+0)*TILE + t] = fmaxf(v.x, 0.f);
        sh_s[(q*4+1)*TILE + t] = fmaxf(v.y, 0.f);
        sh_s[(q*4+2)*TILE + t] = fmaxf(v.z, 0.f);
        sh_s[(q*4+3)*TILE + t] = fmaxf(v.w, 0.f);
    }
    __syncthreads();

    int og = tid >> 3, tg = tid & 7;

    {
        ull a0[8], a1[8];
        ull c0 = pack2(b1[og*2]), c1 = pack2(b1[og*2+1]);
        #pragma unroll
        for (int j = 0; j < 8; ++j) { a0[j] = c0; a1[j] = c1; }
        #pragma unroll 4
        for (int r = 0; r < 64; ++r) {
            ull w0 = pack2(w1[(og*2+0)*64 + r]);
            ull w1v = pack2(w1[(og*2+1)*64 + r]);
            const ull* sv = (const ull*)(sh_s + r*TILE) + tg;
            #pragma unroll
            for (int j = 0; j < 8; ++j) {
                ull s = sv[j*8];
                ffma2(a0[j], w0, s);
                ffma2(a1[j], w1v, s);
            }
        }
        #pragma unroll
        for (int j = 0; j < 8; ++j) {
            float2 v0 = unpack2(a0[j]), v1 = unpack2(a1[j]);
            v0.x = fmaxf(v0.x, 0.f); v0.y = fmaxf(v0.y, 0.f);
            v1.x = fmaxf(v1.x, 0.f); v1.y = fmaxf(v1.y, 0.f);
            *(float2*)(sh_y + (og*2+0)*TILE + 2*(tg + 8*j)) = v0;
            *(float2*)(sh_y + (og*2+1)*TILE + 2*(tg + 8*j)) = v1;
        }
    }
    __syncthreads();

    #pragma unroll 1
    for (int p = 0; p < 2; ++p) {
        int ob = p*128 + og*4;
        ull acc[4][8];
        #pragma unroll
        for (int i = 0; i < 4; ++i) {
            ull bi = pack2(b2[ob + i]);
            #pragma unroll
            for (int j = 0; j < 8; ++j) acc[i][j] = bi;
        }
        #pragma unroll 4
        for (int r = 0; r < 64; ++r) {
            ull w0 = pack2(w2[(ob+0)*64 + r]);
            ull w1v = pack2(w2[(ob+1)*64 + r]);
            ull w2v = pack2(w2[(ob+2)*64 + r]);
            ull w3v = pack2(w2[(ob+3)*64 + r]);
            const ull* yv = (const ull*)(sh_y + r*TILE) + tg;
            #pragma unroll
            for (int j = 0; j < 8; ++j) {
                ull y = yv[j*8];
                ffma2(acc[0][j], w0, y);
                ffma2(acc[1][j], w1v, y);
                ffma2(acc[2][j], w2v, y);
                ffma2(acc[3][j], w3v, y);
            }
        }
        #pragma unroll
        for (int i = 0; i < 4; ++i) {
            float2* row = (float2*)(out + ((size_t)b*OUTC + ob + i)*TLEN + t0);
            #pragma unroll
            for (int j = 0; j < 8; ++j)
                row[tg + 8*j] = unpack2(acc[i][j]);
        }
    }
}

/* ---------------- launch ---------------- */
extern "C" void kernel_launch(void* const* d_in, const int* in_sizes, int n_in,
                              void* d_out, int out_size) {
    (void)in_sizes; (void)n_in; (void)out_size;
    const void*  x       = d_in[0];
    const float* cond    = (const float*)d_in[1];
    const float* first_w = (const float*)d_in[2];
    const float* first_b = (const float*)d_in[3];
    const float* cin_w   = (const float*)d_in[4];
    const float* conv_w  = (const float*)d_in[5];
    const float* conv_b  = (const float*)d_in[6];
    const float* cond_w  = (const float*)d_in[7];
    const float* skip_w  = (const float*)d_in[8];
    const float* skip_b  = (const float*)d_in[9];
    const float* out_w   = (const float*)d_in[10];
    const float* out_b   = (const float*)d_in[11];
    const float* l1w     = (const float*)d_in[12];
    const float* l1b     = (const float*)d_in[13];
    const float* l2w     = (const float*)d_in[14];
    const float* l2b     = (const float*)d_in[15];
    float* out = (float*)d_out;

    cudaFuncSetAttribute(k_layer, cudaFuncAttributeMaxDynamicSharedMemorySize, SMEM_LAYER);
    cudaFuncSetAttribute(k_final, cudaFuncAttributeMaxDynamicSharedMemorySize, SMEM_FINAL);

    k_detect<<<1, 256>>>((const unsigned*)x);
    k_prep_fwt<<<(OUTC*RES + 255)/256, 256>>>(first_w, first_b);
    k_prep_w1<<<(NL*13312 + 255)/256, 256>>>(conv_w, cond_w);
    k_prep_w2<<<(NL*4096 + 255)/256, 256>>>(skip_w, out_w);

    k_upA<<<(BB*CINC*400  + 255)/256, 256>>>(cond, cin_w);
    k_upB<<<(BB*CINC*4000 + 255)/256, 256>>>();
    k_upC<<<(BB*CINC*TLEN + 255)/256, 256>>>();

    k_first<<<(BB*TLEN*16 + 255)/256, 256>>>(x);

    dim3 gridL(TLEN/TT, BB);
    for (int l = 0; l < NL; ++l) {
        int d = 1 << (l % 10);
        k_layer<<<gridL, NTL, SMEM_LAYER>>>(l, d,
            conv_b + l*GATE, skip_b + l*SKC, out_b + l*RES);
    }
    dim3 gridF(TLEN/TILE, BB);
    k_final<<<gridF, NTH, SMEM_FINAL>>>(l1w, l1b, l2w, l2b, out);
}

// round 11
// speedup vs baseline: 2.8096x; 1.8104x over previous
#include <cuda_runtime.h>
#include <cuda_fp16.h>
#include <cuda_bf16.h>
#include <cstdint>

#define BB   8
#define TLEN 32000
#define RES  64
#define GATE 128
#define SKC  64
#define CINC 80
#define NL   30
#define OUTC 256
#define TILE 128      /* head kernel time tile */
#define NTH  256      /* head kernel threads */
#define TT   128      /* layer time tile */
#define NTL  512      /* layer kernel threads (16 warps) */

#define AST2 108      /* ACT stride in half2 units (216 halves, conflict-free) */
#define GST  132      /* gate staging stride (floats) */
#define ZST2 36       /* Z stride in half2 units */
#define SM_Z 67584    /* max(ACT 55296, G 67584) */
#define SMEM_LAYER (SM_Z + TT*ZST2*4)  /* 86016 */
#define SMEM_FINAL (RES*TILE*2*4)      /* 65536 */

typedef unsigned int u32;
typedef unsigned long long ull;

/* ---------------- device scratch ---------------- */
__device__ __align__(256) float g_hA[BB*(size_t)TLEN*RES];    // [b][t][64]
__device__ __align__(256) float g_hB[BB*(size_t)TLEN*RES];
__device__ __align__(256) float g_skip[BB*(size_t)TLEN*SKC];  // [b][t][64]
__device__ __align__(256) float g_c[BB*(size_t)TLEN*CINC];    // [b][t][80]
__device__ __align__(256) float g_cA[BB*CINC*400];
__device__ __align__(256) float g_cB[BB*CINC*4000];
__device__ __align__(256) u32   g_W1pk[NL*13312];  // fp16 frag-packed: [l][ks13][nt16][lane32][2]
__device__ __align__(256) u32   g_W2pk[NL*4096];   // [l][ks4][nt16][lane32][2]
__device__ __align__(256) float g_fwT[OUTC*RES];   // first_w^T + bias
__device__ int g_xflag;

/* ---------------- helpers ---------------- */
__device__ __forceinline__ u32 h2bits(float a, float b) {
    __half2 h = __floats2half2_rn(a, b);
    return *(u32*)&h;
}
__device__ __forceinline__ void mma_f16(float c[4], const u32 a[4], const u32 b[2]) {
    asm volatile("mma.sync.aligned.m16n8k16.row.col.f32.f16.f16.f32 "
        "{%0,%1,%2,%3}, {%4,%5,%6,%7}, {%8,%9}, {%0,%1,%2,%3};"
        : "+f"(c[0]), "+f"(c[1]), "+f"(c[2]), "+f"(c[3])
        : "r"(a[0]), "r"(a[1]), "r"(a[2]), "r"(a[3]), "r"(b[0]), "r"(b[1]));
}
__device__ __forceinline__ float sigf(float x) {
    return __fdividef(1.f, 1.f + __expf(-x));
}
__device__ __forceinline__ float tanhfast(float x) {
    return 2.f * sigf(2.f * x) - 1.f;
}
__device__ __forceinline__ void ffma2(ull& acc, ull ab, ull h2) {
    asm("fma.rn.f32x2 %0, %1, %2, %0;" : "+l"(acc) : "l"(ab), "l"(h2));
}
__device__ __forceinline__ ull pack2(float x) {
    ull r; asm("mov.b64 %0, {%1, %1};" : "=l"(r) : "f"(x)); return r;
}
__device__ __forceinline__ float2 unpack2(ull v) {
    float2 r; asm("mov.b64 {%0, %1}, %2;" : "=f"(r.x), "=f"(r.y) : "l"(v)); return r;
}

/* ---------------- dtype detect ---------------- */
__global__ void k_detect(const unsigned* __restrict__ xu) {
    __shared__ int s_any;
    if (threadIdx.x == 0) s_any = 0;
    __syncthreads();
    int any = 0;
    for (int i = 1 + 2*threadIdx.x; i < BB*TLEN; i += 2*blockDim.x)
        any |= (xu[i] != 0u);
    if (any) atomicOr(&s_any, 1);
    __syncthreads();
    if (threadIdx.x == 0) g_xflag = s_any;
}

/* ---------------- weight prep ---------------- */
__global__ void k_prep_fwt(const float* __restrict__ fw, const float* __restrict__ fb) {
    int i = blockIdx.x*blockDim.x + threadIdx.x;
    if (i >= OUTC*RES) return;
    int xi = i >> 6, o = i & 63;
    g_fwT[i] = fw[o*OUTC + xi] + fb[o];
}

__device__ __forceinline__ float w1_elem(const float* conv_w, const float* cond_w,
                                         int l, int n, int k) {
    if (k < 64)        return conv_w[((l*GATE + n)*RES + k)*2 + 0];
    else if (k < 128)  return conv_w[((l*GATE + n)*RES + (k-64))*2 + 1];
    else               return cond_w[(l*GATE + n)*CINC + (k-128)];
}

__global__ void k_prep_w1(const float* __restrict__ conv_w, const float* __restrict__ cond_w) {
    int i = blockIdx.x*blockDim.x + threadIdx.x;
    if (i >= NL*13312) return;
    int l = i / 13312, r = i % 13312;
    int ks = r >> 10, rem = r & 1023;
    int nt = rem >> 6, rem2 = rem & 63;
    int lane = rem2 >> 1, reg = rem2 & 1;
    int k0 = ks*16 + 2*(lane & 3) + 8*reg;   // 0..207 (even)
    int n  = nt*8 + (lane >> 2);
    g_W1pk[i] = h2bits(w1_elem(conv_w, cond_w, l, n, k0),
                       w1_elem(conv_w, cond_w, l, n, k0 + 1));
}

__global__ void k_prep_w2(const float* __restrict__ skip_w, const float* __restrict__ out_w) {
    int i = blockIdx.x*blockDim.x + threadIdx.x;
    if (i >= NL*4096) return;
    int l = i / 4096, r = i % 4096;
    int ks = r >> 10, rem = r & 1023;
    int nt = rem >> 6, rem2 = rem & 63;
    int lane = rem2 >> 1, reg = rem2 & 1;
    int k0 = ks*16 + 2*(lane & 3) + 8*reg;   // 0..63 (even)
    int n  = nt*8 + (lane >> 2);
    float f0 = (n < 64) ? skip_w[(l*SKC + n)*64 + k0]
                        : out_w[(l*RES + (n-64))*64 + k0];
    float f1 = (n < 64) ? skip_w[(l*SKC + n)*64 + k0 + 1]
                        : out_w[(l*RES + (n-64))*64 + k0 + 1];
    g_W2pk[i] = h2bits(f0, f1);
}

/* ---------------- first conv + skip reset ([b][t][ch]) ---------------- */
__global__ void k_first(const void* __restrict__ xraw) {
    int idx = blockIdx.x*blockDim.x + threadIdx.x;
    if (idx >= BB*TLEN*16) return;
    int q = idx & 15;
    int g = idx >> 4;
    int t = g % TLEN, b = g / TLEN;
    int xi = g_xflag ? ((const int*)xraw)[g]
                     : (int)(((const long long*)xraw)[g]);
    float4 v = ((const float4*)(g_fwT + xi*64))[q];
    size_t off = ((size_t)b*TLEN + t)*64 + q*4;
    *(float4*)(g_hA + off) = v;
    *(float4*)(g_skip + off) = make_float4(0.f, 0.f, 0.f, 0.f);
}

/* ---------------- conditioning upsample ---------------- */
__global__ void k_upA(const float* __restrict__ cond, const float* __restrict__ cin_w) {
    int i = blockIdx.x*blockDim.x + threadIdx.x;
    if (i >= BB*CINC*400) return;
    int f = i % 400, o = (i/400) % CINC, b = i / (CINC*400);
    const float* cp = cond + b*CINC*400 + f;
    const float* wp = cin_w + o*CINC;
    float s = 0.f;
    #pragma unroll 8
    for (int k = 0; k < CINC; ++k) s += wp[k] * cp[k*400];
    g_cA[i] = s;
}
__global__ void k_upB() {
    int i = blockIdx.x*blockDim.x + threadIdx.x;
    if (i >= BB*CINC*4000) return;
    int t = i % 4000, bc = i / 4000;
    int lo = (t-10 < 0) ? 0 : t-10;
    int hi = (t+10 > 3999) ? 3999 : t+10;
    const float* src = g_cA + bc*400;
    float s = 0.f;
    for (int j = lo; j <= hi; ++j) s += src[j/10];
    g_cB[i] = s * (1.f/21.f);
}
__global__ void k_upC() {
    int i = blockIdx.x*blockDim.x + threadIdx.x;
    if (i >= BB*CINC*TLEN) return;
    int t = i % TLEN, bc = i / TLEN;
    int ch = bc % CINC, b = bc / CINC;
    int lo = (t-8 < 0) ? 0 : t-8;
    int hi = (t+8 > TLEN-1) ? TLEN-1 : t+8;
    const float* src = g_cB + bc*4000;
    float s = 0.f;
    for (int j = lo; j <= hi; ++j) s += src[j >> 3];
    g_c[((size_t)b*TLEN + t)*CINC + ch] = s * (1.f/17.f);
}

/* ---------------- fp16 mma.sync layer kernel (occupancy 2) ---------------- */
__global__ void __launch_bounds__(NTL, 2) k_layer(int l, int d,
        const float* __restrict__ conv_b,
        const float* __restrict__ skip_b,
        const float* __restrict__ out_b) {
    extern __shared__ __align__(16) char smx[];
    u32*   ACT2 = (u32*)smx;               // [128][AST2] half2; becomes G after stage1
    float* G    = (float*)smx;             // [128][GST]
    u32*   Z2   = (u32*)(smx + SM_Z);      // [128][ZST2] half2

    int tid = threadIdx.x, lane = tid & 31, wid = tid >> 5;
    int gid = lane >> 2, tig = lane & 3;
    int tg = wid & 3, cg = wid >> 2;       // 4 time-groups x 4 channel-groups
    int b = blockIdx.y, t0 = blockIdx.x * TT;

    const float* hin  = ((l & 1) ? g_hB : g_hA) + (size_t)b*TLEN*64;
    float*       hout = ((l & 1) ? g_hA : g_hB) + (size_t)b*TLEN*64;
    const float* cbp  = g_c + (size_t)b*TLEN*CINC;

    /* ---- assemble ACT [t][k<208 halves]: three uniform loops (batched LDG) ---- */
    /* region 1: h(t-d), k halves 0..63 -> quads 0..15   (2048 items, 4/thread) */
    #pragma unroll
    for (int it = 0; it < 4; ++it) {
        int idx = tid + it*NTL;
        int t = idx >> 4, q = idx & 15;
        int ts = t0 + t - d;
        float4 v = make_float4(0.f, 0.f, 0.f, 0.f);
        if (ts >= 0) v = *(const float4*)(hin + (size_t)ts*64 + q*4);
        *(uint2*)(ACT2 + t*AST2 + q*2) =
            make_uint2(h2bits(v.x, v.y), h2bits(v.z, v.w));
    }
    /* region 2: h(t), quads 16..31 */
    #pragma unroll
    for (int it = 0; it < 4; ++it) {
        int idx = tid + it*NTL;
        int t = idx >> 4, q = idx & 15;
        float4 v = *(const float4*)(hin + (size_t)(t0 + t)*64 + q*4);
        *(uint2*)(ACT2 + t*AST2 + (q + 16)*2) =
            make_uint2(h2bits(v.x, v.y), h2bits(v.z, v.w));
    }
    /* region 3: c, quads 32..51 (2560 items, 5/thread) */
    #pragma unroll
    for (int it = 0; it < 5; ++it) {
        int idx = tid + it*NTL;
        int t = idx / 20, q = idx % 20;
        float4 v = *(const float4*)(cbp + (size_t)(t0 + t)*CINC + q*4);
        *(uint2*)(ACT2 + t*AST2 + (q + 32)*2) =
            make_uint2(h2bits(v.x, v.y), h2bits(v.z, v.w));
    }
    __syncthreads();

    /* ---- stage 1: D1[128 t][128 gate ch], K=208 (13 k-steps) ---- */
    float acc[2][4][4];
    #pragma unroll
    for (int i = 0; i < 2; ++i)
        #pragma unroll
        for (int j = 0; j < 4; ++j)
            #pragma unroll
            for (int r = 0; r < 4; ++r) acc[i][j][r] = 0.f;

    const u32* W1p = g_W1pk + (size_t)l*13312;
    #pragma unroll 1
    for (int ks = 0; ks < 13; ++ks) {
        u32 a[2][4];
        int kk = ks*8 + tig;               // half2 index
        #pragma unroll
        for (int i = 0; i < 2; ++i) {
            int m = (tg*2 + i)*16 + gid;
            a[i][0] = ACT2[m*AST2 + kk];
            a[i][1] = ACT2[(m+8)*AST2 + kk];
            a[i][2] = ACT2[m*AST2 + kk + 4];
            a[i][3] = ACT2[(m+8)*AST2 + kk + 4];
        }
        #pragma unroll
        for (int j = 0; j < 4; ++j) {
            int nt = cg*4 + j;
            uint2 bv = __ldg((const uint2*)(W1p + ((ks*16 + nt)*32 + lane)*2));
            u32 bb[2] = {bv.x, bv.y};
            mma_f16(acc[0][j], a[0], bb);
            mma_f16(acc[1][j], a[1], bb);
        }
    }
    __syncthreads();   /* all ACT reads complete before G overwrite */

    /* ---- epilogue 1: write gates to G ---- */
    #pragma unroll
    for (int i = 0; i < 2; ++i) {
        int m0 = (tg*2 + i)*16 + gid;
        #pragma unroll
        for (int j = 0; j < 4; ++j) {
            int n0 = cg*32 + j*8 + 2*tig;
            *(float2*)&G[m0*GST + n0]     = make_float2(acc[i][j][0], acc[i][j][1]);
            *(float2*)&G[(m0+8)*GST + n0] = make_float2(acc[i][j][2], acc[i][j][3]);
        }
    }
    __syncthreads();

    /* ---- gate: z = tanh(a)*sigmoid(b) -> Z (half2) ---- */
    for (int idx = tid; idx < TT*32; idx += NTL) {
        int t = idx >> 5, c2 = idx & 31;
        int ch = c2*2;
        float a0 = G[t*GST + ch]     + conv_b[ch];
        float a1 = G[t*GST + ch + 1] + conv_b[ch + 1];
        float b0 = G[t*GST + 64 + ch]     + conv_b[64 + ch];
        float b1 = G[t*GST + 64 + ch + 1] + conv_b[64 + ch + 1];
        Z2[t*ZST2 + c2] = h2bits(tanhfast(a0) * sigf(b0),
                                 tanhfast(a1) * sigf(b1));
    }
    __syncthreads();

    /* ---- stage 2: D2[128 t][skip64|out64], K=64 (4 k-steps) ---- */
    float acc2[2][4][4];
    #pragma unroll
    for (int i = 0; i < 2; ++i)
        #pragma unroll
        for (int j = 0; j < 4; ++j)
            #pragma unroll
            for (int r = 0; r < 4; ++r) acc2[i][j][r] = 0.f;

    const u32* W2p = g_W2pk + (size_t)l*4096;
    #pragma unroll
    for (int ks = 0; ks < 4; ++ks) {
        u32 a[2][4];
        int kk = ks*8 + tig;
        #pragma unroll
        for (int i = 0; i < 2; ++i) {
            int m = (tg*2 + i)*16 + gid;
            a[i][0] = Z2[m*ZST2 + kk];
            a[i][1] = Z2[(m+8)*ZST2 + kk];
            a[i][2] = Z2[m*ZST2 + kk + 4];
            a[i][3] = Z2[(m+8)*ZST2 + kk + 4];
        }
        #pragma unroll
        for (int j = 0; j < 4; ++j) {
            int nt = cg*4 + j;
            uint2 bv = __ldg((const uint2*)(W2p + ((ks*16 + nt)*32 + lane)*2));
            u32 bb[2] = {bv.x, bv.y};
            mma_f16(acc2[0][j], a[0], bb);
            mma_f16(acc2[1][j], a[1], bb);
        }
    }

    /* ---- epilogue 2: skip RMW + residual h ---- */
    #pragma unroll
    for (int i = 0; i < 2; ++i) {
        int m0 = (tg*2 + i)*16 + gid;
        #pragma unroll
        for (int j = 0; j < 4; ++j) {
            int n0 = cg*32 + j*8 + 2*tig;
            #pragma unroll
            for (int h2 = 0; h2 < 2; ++h2) {
                int t = t0 + m0 + 8*h2;
                float v0 = acc2[i][j][2*h2], v1 = acc2[i][j][2*h2 + 1];
                if (n0 < 64) {
                    float2* sp = (float2*)&g_skip[((size_t)b*TLEN + t)*64 + n0];
                    float2 cur = *sp;
                    cur.x += v0 + skip_b[n0];
                    cur.y += v1 + skip_b[n0 + 1];
                    *sp = cur;
                } else {
                    int o = n0 - 64;
                    float2 hv = *(const float2*)&hin[(size_t)t*64 + o];
                    float2 r = make_float2(hv.x + v0 + out_b[o],
                                           hv.y + v1 + out_b[o + 1]);
                    *(float2*)&hout[(size_t)t*64 + o] = r;
                }
            }
        }
    }
}

/* ---------------- output head (FFMA2, transpose-load skip) ---------------- */
__global__ void __launch_bounds__(NTH) k_final(const float* __restrict__ w1,
                                               const float* __restrict__ b1,
                                               const float* __restrict__ w2,
                                               const float* __restrict__ b2,
                                               float* __restrict__ out) {
    extern __shared__ float sm[];
    float* sh_s = sm;              // relu(skips) [64][128]
    float* sh_y = sm + RES*TILE;   // relu(y1)    [64][128]
    int b = blockIdx.y, t0 = blockIdx.x * TILE, tid = threadIdx.x;

    for (int idx = tid; idx < 16*TILE; idx += NTH) {
        int t = idx & (TILE-1), q = idx >> 7;
        float4 v = *(const float4*)(g_skip + ((size_t)b*TLEN + t0 + t)*64 + q*4);
        sh_s[(q*4+0)*TILE + t] = fmaxf(v.x, 0.f);
        sh_s[(q*4+1)*TILE + t] = fmaxf(v.y, 0.f);
        sh_s[(q*4+2)*TILE + t] = fmaxf(v.z, 0.f);
        sh_s[(q*4+3)*TILE + t] = fmaxf(v.w, 0.f);
    }
    __syncthreads();

    int og = tid >> 3, tg = tid & 7;

    {
        ull a0[8], a1[8];
        ull c0 = pack2(b1[og*2]), c1 = pack2(b1[og*2+1]);
        #pragma unroll
        for (int j = 0; j < 8; ++j) { a0[j] = c0; a1[j] = c1; }
        #pragma unroll 4
        for (int r = 0; r < 64; ++r) {
            ull w0 = pack2(w1[(og*2+0)*64 + r]);
            ull w1v = pack2(w1[(og*2+1)*64 + r]);
            const ull* sv = (const ull*)(sh_s + r*TILE) + tg;
            #pragma unroll
            for (int j = 0; j < 8; ++j) {
                ull s = sv[j*8];
                ffma2(a0[j], w0, s);
                ffma2(a1[j], w1v, s);
            }
        }
        #pragma unroll
        for (int j = 0; j < 8; ++j) {
            float2 v0 = unpack2(a0[j]), v1 = unpack2(a1[j]);
            v0.x = fmaxf(v0.x, 0.f); v0.y = fmaxf(v0.y, 0.f);
            v1.x = fmaxf(v1.x, 0.f); v1.y = fmaxf(v1.y, 0.f);
            *(float2*)(sh_y + (og*2+0)*TILE + 2*(tg + 8*j)) = v0;
            *(float2*)(sh_y + (og*2+1)*TILE + 2*(tg + 8*j)) = v1;
        }
    }
    __syncthreads();

    #pragma unroll 1
    for (int p = 0; p < 2; ++p) {
        int ob = p*128 + og*4;
        ull acc[4][8];
        #pragma unroll
        for (int i = 0; i < 4; ++i) {
            ull bi = pack2(b2[ob + i]);
            #pragma unroll
            for (int j = 0; j < 8; ++j) acc[i][j] = bi;
        }
        #pragma unroll 4
        for (int r = 0; r < 64; ++r) {
            ull w0 = pack2(w2[(ob+0)*64 + r]);
            ull w1v = pack2(w2[(ob+1)*64 + r]);
            ull w2v = pack2(w2[(ob+2)*64 + r]);
            ull w3v = pack2(w2[(ob+3)*64 + r]);
            const ull* yv = (const ull*)(sh_y + r*TILE) + tg;
            #pragma unroll
            for (int j = 0; j < 8; ++j) {
                ull y = yv[j*8];
                ffma2(acc[0][j], w0, y);
                ffma2(acc[1][j], w1v, y);
                ffma2(acc[2][j], w2v, y);
                ffma2(acc[3][j], w3v, y);
            }
        }
        #pragma unroll
        for (int i = 0; i < 4; ++i) {
            float2* row = (float2*)(out + ((size_t)b*OUTC + ob + i)*TLEN + t0);
            #pragma unroll
            for (int j = 0; j < 8; ++j)
                row[tg + 8*j] = unpack2(acc[i][j]);
        }
    }
}

/* ---------------- launch ---------------- */
extern "C" void kernel_launch(void* const* d_in, const int* in_sizes, int n_in,
                              void* d_out, int out_size) {
    (void)in_sizes; (void)n_in; (void)out_size;
    const void*  x       = d_in[0];
    const float* cond    = (const float*)d_in[1];
    const float* first_w = (const float*)d_in[2];
    const float* first_b = (const float*)d_in[3];
    const float* cin_w   = (const float*)d_in[4];
    const float* conv_w  = (const float*)d_in[5];
    const float* conv_b  = (const float*)d_in[6];
    const float* cond_w  = (const float*)d_in[7];
    const float* skip_w  = (const float*)d_in[8];
    const float* skip_b  = (const float*)d_in[9];
    const float* out_w   = (const float*)d_in[10];
    const float* out_b   = (const float*)d_in[11];
    const float* l1w     = (const float*)d_in[12];
    const float* l1b     = (const float*)d_in[13];
    const float* l2w     = (const float*)d_in[14];
    const float* l2b     = (const float*)d_in[15];
    float* out = (float*)d_out;

    cudaFuncSetAttribute(k_layer, cudaFuncAttributeMaxDynamicSharedMemorySize, SMEM_LAYER);
    cudaFuncSetAttribute(k_final, cudaFuncAttributeMaxDynamicSharedMemorySize, SMEM_FINAL);

    k_detect<<<1, 256>>>((const unsigned*)x);
    k_prep_fwt<<<(OUTC*RES + 255)/256, 256>>>(first_w, first_b);
    k_prep_w1<<<(NL*13312 + 255)/256, 256>>>(conv_w, cond_w);
    k_prep_w2<<<(NL*4096 + 255)/256, 256>>>(skip_w, out_w);

    k_upA<<<(BB*CINC*400  + 255)/256, 256>>>(cond, cin_w);
    k_upB<<<(BB*CINC*4000 + 255)/256, 256>>>();
    k_upC<<<(BB*CINC*TLEN + 255)/256, 256>>>();

    k_first<<<(BB*TLEN*16 + 255)/256, 256>>>(x);

    dim3 gridL(TLEN/TT, BB);
    for (int l = 0; l < NL; ++l) {
        int d = 1 << (l % 10);
        k_layer<<<gridL, NTL, SMEM_LAYER>>>(l, d,
            conv_b + l*GATE, skip_b + l*SKC, out_b + l*RES);
    }
    dim3 gridF(TLEN/TILE, BB);
    k_final<<<gridF, NTH, SMEM_FINAL>>>(l1w, l1b, l2w, l2b, out);
}